// round 3
// baseline (speedup 1.0000x reference)
#include <cuda_runtime.h>
#include <cstdint>

#define NGROUPS 8
#define NTHREADS 256

__global__ void __launch_bounds__(NTHREADS)
fd_sample_kernel(const float* __restrict__ q0,
                 const float* __restrict__ qg,
                 const float* __restrict__ noise0,
                 const float* __restrict__ noise,
                 float* __restrict__ out,
                 int n)
{
    // Stage tiny probability tables in shared memory (456 floats).
    __shared__ float s_q0[8];
    __shared__ float s_qg[(NGROUPS - 1) * 64];
    for (int t = threadIdx.x; t < 8; t += NTHREADS) s_q0[t] = q0[t];
    for (int t = threadIdx.x; t < (NGROUPS - 1) * 64; t += NTHREADS) s_qg[t] = qg[t];
    __syncthreads();

    int i = blockIdx.x * NTHREADS + threadIdx.x;
    if (i >= n) return;

    // ---- group 0: argmax over q0 + noise0[i] (8 contiguous floats) ----
    const float4* p0 = reinterpret_cast<const float4*>(noise0) + (size_t)i * 2;
    float4 a = p0[0];
    float4 b = p0[1];
    float v[8];
    v[0] = a.x; v[1] = a.y; v[2] = a.z; v[3] = a.w;
    v[4] = b.x; v[5] = b.y; v[6] = b.z; v[7] = b.w;

    int best = 0;
    float bv = v[0] + s_q0[0];
#pragma unroll
    for (int j = 1; j < 8; j++) {
        float x = v[j] + s_q0[j];
        if (x > bv) { bv = x; best = j; }   // strict > == first-max (jnp.argmax)
    }

    float bits[NGROUPS * 3];
    bits[0] = (float)((best >> 2) & 1);
    bits[1] = (float)((best >> 1) & 1);
    bits[2] = (float)(best & 1);

    // ---- groups 1..G-1: conditional slice selected by previous argmax ----
    const size_t gstride = (size_t)n * 8;   // floats per group in `noise`
#pragma unroll
    for (int g = 0; g < NGROUPS - 1; g++) {
        const float4* pg =
            reinterpret_cast<const float4*>(noise + (size_t)g * gstride) + (size_t)i * 2;
        float4 c = pg[0];
        float4 d = pg[1];
        v[0] = c.x; v[1] = c.y; v[2] = c.z; v[3] = c.w;
        v[4] = d.x; v[5] = d.y; v[6] = d.z; v[7] = d.w;

        // previous argmax index IS the flattened conditioning index:
        // offset = c0*32 + c1*16 + c2*8 = best*8 within the 64-float table
        const float* tbl = &s_qg[g * 64 + best * 8];
        int nb = 0;
        float nbv = v[0] + tbl[0];
#pragma unroll
        for (int j = 1; j < 8; j++) {
            float x = v[j] + tbl[j];
            if (x > nbv) { nbv = x; nb = j; }
        }
        best = nb;
        bits[3 + g * 3 + 0] = (float)((best >> 2) & 1);
        bits[3 + g * 3 + 1] = (float)((best >> 1) & 1);
        bits[3 + g * 3 + 2] = (float)(best & 1);
    }

    // ---- write 24 floats = 6 x float4 (row start i*96 B is 16B-aligned) ----
    float4* po = reinterpret_cast<float4*>(out + (size_t)i * 24);
#pragma unroll
    for (int k = 0; k < 6; k++) {
        po[k] = make_float4(bits[k * 4 + 0], bits[k * 4 + 1],
                            bits[k * 4 + 2], bits[k * 4 + 3]);
    }
}

extern "C" void kernel_launch(void* const* d_in, const int* in_sizes, int n_in,
                              void* d_out, int out_size)
{
    // Identify inputs by element count — robust to harness input ordering.
    //   q0:      8 floats
    //   qg:      (G-1)*64 = 448 floats
    //   noise0:  N*8 floats
    //   noise:   (G-1)*N*8 floats  (the largest array)
    const float* q0 = nullptr;
    const float* qg = nullptr;
    const float* noise0 = nullptr;
    const float* noise = nullptr;
    long long n0_sz = 0;

    for (int k = 0; k < n_in; k++) {
        long long sz = in_sizes[k];
        const float* p = (const float*)d_in[k];
        if (sz == 8) {
            q0 = p;
        } else if (sz == (NGROUPS - 1) * 64) {
            qg = p;
        } else {
            // big arrays: smaller -> noise0, larger -> noise
            if (noise0 == nullptr) { noise0 = p; n0_sz = sz; }
            else if (sz > n0_sz)   { noise = p; }
            else { noise = noise0; noise0 = p; n0_sz = sz; }
        }
    }

    const int n = (int)(n0_sz / 8);   // N samples
    const int blocks = (n + NTHREADS - 1) / NTHREADS;
    fd_sample_kernel<<<blocks, NTHREADS>>>(q0, qg, noise0, noise,
                                           (float*)d_out, n);
}

// round 4
// speedup vs baseline: 1.0330x; 1.0330x over previous
#include <cuda_runtime.h>
#include <cstdint>

#define NGROUPS 8
#define NTHREADS 256

__global__ void __launch_bounds__(NTHREADS, 3)
fd_sample_kernel(const float* __restrict__ q0,
                 const float* __restrict__ qg,
                 const float* __restrict__ noise0,
                 const float* __restrict__ noise,
                 float* __restrict__ out,
                 int n)
{
    // Stage tiny probability tables in shared memory (456 floats).
    __shared__ float s_q0[8];
    __shared__ float s_qg[(NGROUPS - 1) * 64];
    for (int t = threadIdx.x; t < 8; t += NTHREADS) s_q0[t] = q0[t];
    for (int t = threadIdx.x; t < (NGROUPS - 1) * 64; t += NTHREADS) s_qg[t] = qg[t];
    __syncthreads();

    int i = blockIdx.x * NTHREADS + threadIdx.x;
    if (i >= n) return;

    // ---- prefetch ALL noise for this sample: 16 independent LDG.128 ----
    // (addresses are known upfront; batching them gives MLP=16 per thread so
    //  DRAM latency is covered even at reduced occupancy)
    float4 vv[2 * NGROUPS];
    {
        const float4* p0 = reinterpret_cast<const float4*>(noise0) + (size_t)i * 2;
        vv[0] = p0[0];
        vv[1] = p0[1];
        const size_t gstride = (size_t)n * 8;   // floats per group in `noise`
#pragma unroll
        for (int g = 0; g < NGROUPS - 1; g++) {
            const float4* pg =
                reinterpret_cast<const float4*>(noise + (size_t)g * gstride) + (size_t)i * 2;
            vv[2 + g * 2] = pg[0];
            vv[3 + g * 2] = pg[1];
        }
    }

    // ---- chained Gumbel-max argmax over the 8 groups ----
    float bits[NGROUPS * 3];
    int best = 0;
#pragma unroll
    for (int g = 0; g < NGROUPS; g++) {
        // group 0 uses q0; group g>=1 uses conditional slice qg[g-1][best]
        // (previous argmax index IS the flattened C-order conditioning index)
        const float* tbl = (g == 0) ? s_q0 : &s_qg[(g - 1) * 64 + best * 8];
        float4 a = vv[g * 2 + 0];
        float4 b = vv[g * 2 + 1];
        float v[8];
        v[0] = a.x; v[1] = a.y; v[2] = a.z; v[3] = a.w;
        v[4] = b.x; v[5] = b.y; v[6] = b.z; v[7] = b.w;

        int nb = 0;
        float nbv = v[0] + tbl[0];
#pragma unroll
        for (int j = 1; j < 8; j++) {
            float x = v[j] + tbl[j];
            if (x > nbv) { nbv = x; nb = j; }   // strict > == first-max (jnp.argmax)
        }
        best = nb;
        bits[g * 3 + 0] = (float)((best >> 2) & 1);
        bits[g * 3 + 1] = (float)((best >> 1) & 1);
        bits[g * 3 + 2] = (float)(best & 1);
    }

    // ---- write 24 floats = 6 x float4 (row start i*96 B is 16B-aligned) ----
    float4* po = reinterpret_cast<float4*>(out + (size_t)i * 24);
#pragma unroll
    for (int k = 0; k < 6; k++) {
        po[k] = make_float4(bits[k * 4 + 0], bits[k * 4 + 1],
                            bits[k * 4 + 2], bits[k * 4 + 3]);
    }
}

extern "C" void kernel_launch(void* const* d_in, const int* in_sizes, int n_in,
                              void* d_out, int out_size)
{
    // Identify inputs by element count — robust to harness input ordering.
    //   q0:      8 floats
    //   qg:      (G-1)*64 = 448 floats
    //   noise0:  N*8 floats
    //   noise:   (G-1)*N*8 floats  (the largest array)
    const float* q0 = nullptr;
    const float* qg = nullptr;
    const float* noise0 = nullptr;
    const float* noise = nullptr;
    long long n0_sz = 0;

    for (int k = 0; k < n_in; k++) {
        long long sz = in_sizes[k];
        const float* p = (const float*)d_in[k];
        if (sz == 8) {
            q0 = p;
        } else if (sz == (NGROUPS - 1) * 64) {
            qg = p;
        } else {
            if (noise0 == nullptr) { noise0 = p; n0_sz = sz; }
            else if (sz > n0_sz)   { noise = p; }
            else { noise = noise0; noise0 = p; n0_sz = sz; }
        }
    }

    const int n = (int)(n0_sz / 8);   // N samples
    const int blocks = (n + NTHREADS - 1) / NTHREADS;
    fd_sample_kernel<<<blocks, NTHREADS>>>(q0, qg, noise0, noise,
                                           (float*)d_out, n);
}